// round 15
// baseline (speedup 1.0000x reference)
#include <cuda_runtime.h>
#include <cstdint>

// ---------------------------------------------------------------------------
// out = BN( sign(x) @ sign(W)^T ),  x[8192,2048], W[2048,2048] fp32.
// tcgen05 unavailable (harness assembles sm_103). Hybrid two-engine GEMM:
// tensor CTAs (mma.sync, bids 0..147) + dp4a CTAs (fma pipe, bids 148..295)
// pulling 128x128 tiles from one atomic queue. R14 showed dp4a warps stalled
// ~50% on LDS latency (strided-map change neutral -> not bank conflicts).
// This round: dp4a operands are register double-buffered so kw+1's LDS
// overlap kw's 64-dp4a chain. Stats exact ints -> bit-identical output.
// ---------------------------------------------------------------------------

static constexpr int Mdim = 8192;
static constexpr int Ndim = 2048;
static constexpr int Kdim = 2048;

__device__ int8_t  g_xa[(size_t)Mdim * Kdim];          // 16 MB
__device__ int8_t  g_wa[(size_t)Ndim * Kdim];          //  4 MB
__device__ int16_t g_gemm16[(size_t)Mdim * Ndim];      // 32 MB (|val| <= 2048)
__device__ int     g_psum_i[128 * Ndim];               // per-64-row partials
__device__ int     g_psq_i [128 * Ndim];               // (exact int32)
__device__ float   g_scale[Ndim];
__device__ float   g_shift[Ndim];
__device__ int     g_next;                             // tile work queue

// ---------------------------------------------------------------------------
// Helpers
// ---------------------------------------------------------------------------
__device__ __forceinline__ uint32_t smem_u32(const void* p) {
    uint32_t r;
    asm("{ .reg .u64 t; cvta.to.shared.u64 t, %1; cvt.u32.u64 %0, t; }"
        : "=r"(r) : "l"(p));
    return r;
}

__device__ __forceinline__ void cp16(uint32_t saddr, const void* gaddr) {
    asm volatile("cp.async.cg.shared.global [%0], [%1], 16;"
                 :: "r"(saddr), "l"(gaddr));
}

// SW64 swizzle for 64-byte rows: bits[5:4] ^= bits[8:7]
__device__ __forceinline__ uint32_t swz64(uint32_t off) {
    return off ^ ((off >> 3) & 0x30);
}

#define LDSM_X4(R0, R1, R2, R3, addr)                                        \
    asm volatile("ldmatrix.sync.aligned.m8n8.x4.shared.b16 {%0,%1,%2,%3}, [%4];" \
                 : "=r"(R0), "=r"(R1), "=r"(R2), "=r"(R3) : "r"(addr))

__device__ __forceinline__ void mma_s8(int& c0, int& c1, int& c2, int& c3,
                                       uint32_t a0, uint32_t a1, uint32_t a2,
                                       uint32_t a3, uint32_t b0, uint32_t b1) {
    asm volatile(
        "mma.sync.aligned.m16n8k32.row.col.s32.s8.s8.s32 "
        "{%0,%1,%2,%3}, {%4,%5,%6,%7}, {%8,%9}, {%0,%1,%2,%3};"
        : "+r"(c0), "+r"(c1), "+r"(c2), "+r"(c3)
        : "r"(a0), "r"(a1), "r"(a2), "r"(a3), "r"(b0), "r"(b1));
}

// ---------------------------------------------------------------------------
// Kernels 1/2: binarize fp32 -> int8 {-1, 0, +1}
// ---------------------------------------------------------------------------
__device__ __forceinline__ int8_t sgn8(float a) {
    return (int8_t)((a > 0.0f) ? 1 : ((a < 0.0f) ? -1 : 0));
}

__global__ void binx_kernel(const float4* __restrict__ in) {
    int i = blockIdx.x * blockDim.x + threadIdx.x;
    float4 v = in[i];
    reinterpret_cast<char4*>(g_xa)[i] =
        make_char4(sgn8(v.x), sgn8(v.y), sgn8(v.z), sgn8(v.w));
}

__global__ void binw_kernel(const float4* __restrict__ in) {
    int i = blockIdx.x * blockDim.x + threadIdx.x;
    float4 v = in[i];
    reinterpret_cast<char4*>(g_wa)[i] =
        make_char4(sgn8(v.x), sgn8(v.y), sgn8(v.z), sgn8(v.w));
}

// Resets the work queue each graph replay (also keeps GEMM at ncu slot 4).
__global__ void pad_kernel() {
    if (threadIdx.x == 0) g_next = 0;
}

// ---------------------------------------------------------------------------
// Kernel 4: hybrid persistent GEMM, D = Xa @ Wa^T over 1024 128x128 tiles.
// ---------------------------------------------------------------------------
static constexpr int BM = 128, BN = 128, BK = 64, STAGES = 4;
static constexpr int KT = Kdim / BK;                      // 32 ktiles / tile
static constexpr int NSM = 148;
static constexpr int NTILES = (Mdim / BM) * (Ndim / BN);  // 1024
static constexpr int A_BYTES = BM * BK;                   // 8 KB
static constexpr int B_BYTES = BN * BK;                   // 8 KB
static constexpr int STAGE_BYTES = A_BYTES + B_BYTES;     // 16 KB
// dp4a layout: per buffer, X half 128 rows x 144B (128B data + pad) then W.
static constexpr int XROW  = 144;
static constexpr int WOFF  = 128 * XROW;                  // 18432
static constexpr int DBUF  = 2 * WOFF;                    // 36864 per buffer
static constexpr int GEMM_SMEM = 2 * DBUF;                // 73728 (dyn)

__global__ void __launch_bounds__(256, 2)
gemm_kernel() {
    extern __shared__ __align__(1024) char smraw[];
    __shared__ int sh_next;

    const int tid  = threadIdx.x;
    const int lane = tid & 31;
    const uint32_t smBase = smem_u32(smraw);

    if (blockIdx.x < NSM) {
        // =================== TENSOR PATH ===================
        const int wid  = tid >> 5;
        const int warpM = wid >> 2;            // 0..1 -> 64 rows
        const int warpN = wid & 3;             // 0..3 -> 32 cols

        if (tid == 0) sh_next = atomicAdd(&g_next, 1);
        __syncthreads();
        int cur = sh_next;
        if (cur >= NTILES) return;

        auto load_ts = [&](int s, int t, int kt) {
            const int8_t* gA = g_xa + (size_t)(t >> 4) * BM * Kdim + kt * BK;
            const int8_t* gB = g_wa + (size_t)(t & 15) * BN * Kdim + kt * BK;
            uint32_t aBase = smBase + (uint32_t)s * STAGE_BYTES;
            uint32_t bBase = aBase + A_BYTES;
            #pragma unroll
            for (int i = 0; i < 2; i++) {
                int c = i * 256 + tid;
                int row = c >> 2, seg = c & 3;
                cp16(aBase + swz64((uint32_t)c * 16),
                     gA + (size_t)row * Kdim + seg * 16);
            }
            #pragma unroll
            for (int i = 0; i < 2; i++) {
                int c = i * 256 + tid;
                int row = c >> 2, seg = c & 3;
                cp16(bBase + swz64((uint32_t)c * 16),
                     gB + (size_t)row * Kdim + seg * 16);
            }
            asm volatile("cp.async.commit_group;" ::: "memory");
        };

        const int lrow = (lane & 7) + (((lane >> 3) & 1) << 3);
        const int lkb  = ((lane >> 4) & 1) * 16;
        uint32_t aoff[4], boff[2];
        #pragma unroll
        for (int mi = 0; mi < 4; mi++)
            aoff[mi] = (uint32_t)(warpM * 64 + mi * 16 + lrow) * BK + lkb;
        #pragma unroll
        for (int pb = 0; pb < 2; pb++)
            boff[pb] = (uint32_t)(warpN * 32 + pb * 16 + lrow) * BK + lkb;

        int acc[4][4][4];
        #pragma unroll
        for (int mi = 0; mi < 4; mi++)
            #pragma unroll
            for (int ni = 0; ni < 4; ni++)
                #pragma unroll
                for (int r = 0; r < 4; r++) acc[mi][ni][r] = 0;

        const int erow = lane >> 2;
        const int ecol = (lane & 3) * 2;

        #pragma unroll
        for (int s = 0; s < STAGES - 1; s++) load_ts(s, cur, s);

        int nxt = NTILES;
        while (true) {
            for (int kt = 0; kt < KT; kt++) {
                const int s = kt & (STAGES - 1);
                asm volatile("cp.async.wait_group %0;" :: "n"(STAGES - 2)
                             : "memory");
                __syncthreads();

                const int np = kt + STAGES - 1;
                const int ls = np & (STAGES - 1);
                if (np < KT) {
                    load_ts(ls, cur, np);
                } else {
                    if (np == KT) nxt = sh_next;   // fetched at kt == KT-4
                    if (nxt < NTILES)
                        load_ts(ls, nxt, np - KT);
                    else
                        asm volatile("cp.async.commit_group;" ::: "memory");
                }
                if (kt == KT - 4 && tid == 0)
                    sh_next = atomicAdd(&g_next, 1);

                const uint32_t aBase = smBase + (uint32_t)s * STAGE_BYTES;
                const uint32_t bBase = aBase + A_BYTES;
                #pragma unroll
                for (int k32 = 0; k32 < 2; k32++) {
                    uint32_t a[4][4], b[2][4];
                    #pragma unroll
                    for (int mi = 0; mi < 4; mi++)
                        LDSM_X4(a[mi][0], a[mi][1], a[mi][2], a[mi][3],
                                aBase + swz64(aoff[mi] + k32 * 32));
                    #pragma unroll
                    for (int pb = 0; pb < 2; pb++)
                        LDSM_X4(b[pb][0], b[pb][1], b[pb][2], b[pb][3],
                                bBase + swz64(boff[pb] + k32 * 32));
                    #pragma unroll
                    for (int mi = 0; mi < 4; mi++) {
                        #pragma unroll
                        for (int ni = 0; ni < 4; ni++) {
                            const int pb = ni >> 1, sub = ni & 1;
                            mma_s8(acc[mi][ni][0], acc[mi][ni][1],
                                   acc[mi][ni][2], acc[mi][ni][3],
                                   a[mi][0], a[mi][1], a[mi][2], a[mi][3],
                                   b[pb][sub], b[pb][2 + sub]);
                        }
                    }
                }
            }

            // ---- tile epilogue: int16 store + exact int column stats ----
            {
                const int tileM = cur >> 4, tileN = cur & 15;
                const int rowBase = tileM * BM + warpM * 64;
                const int colBase = tileN * BN + warpN * 32;
                int16_t* gout = g_gemm16 + (size_t)rowBase * Ndim + colBase;
                #pragma unroll
                for (int mi = 0; mi < 4; mi++) {
                    #pragma unroll
                    for (int ni = 0; ni < 4; ni++) {
                        int16_t* p0 = gout + (size_t)(mi * 16 + erow) * Ndim
                                    + ni * 8 + ecol;
                        *reinterpret_cast<short2*>(p0) =
                            make_short2((int16_t)acc[mi][ni][0],
                                        (int16_t)acc[mi][ni][1]);
                        *reinterpret_cast<short2*>(p0 + (size_t)8 * Ndim) =
                            make_short2((int16_t)acc[mi][ni][2],
                                        (int16_t)acc[mi][ni][3]);
                    }
                }
                const int chunk = tileM * 2 + warpM;
                #pragma unroll
                for (int ni = 0; ni < 4; ni++) {
                    int s0 = 0, s1 = 0, q0 = 0, q1 = 0;
                    #pragma unroll
                    for (int mi = 0; mi < 4; mi++) {
                        int a0 = acc[mi][ni][0], a1 = acc[mi][ni][1];
                        int a2 = acc[mi][ni][2], a3 = acc[mi][ni][3];
                        s0 += a0 + a2;  s1 += a1 + a3;
                        q0 += a0 * a0 + a2 * a2;
                        q1 += a1 * a1 + a3 * a3;
                    }
                    #pragma unroll
                    for (int off = 4; off < 32; off <<= 1) {
                        s0 += __shfl_xor_sync(0xffffffffu, s0, off);
                        s1 += __shfl_xor_sync(0xffffffffu, s1, off);
                        q0 += __shfl_xor_sync(0xffffffffu, q0, off);
                        q1 += __shfl_xor_sync(0xffffffffu, q1, off);
                    }
                    if (lane < 4) {
                        int c = colBase + ni * 8 + lane * 2;
                        g_psum_i[(size_t)chunk * Ndim + c]     = s0;
                        g_psum_i[(size_t)chunk * Ndim + c + 1] = s1;
                        g_psq_i [(size_t)chunk * Ndim + c]     = q0;
                        g_psq_i [(size_t)chunk * Ndim + c + 1] = q1;
                    }
                }
                #pragma unroll
                for (int mi = 0; mi < 4; mi++)
                    #pragma unroll
                    for (int ni = 0; ni < 4; ni++)
                        #pragma unroll
                        for (int r = 0; r < 4; r++) acc[mi][ni][r] = 0;
            }

            if (nxt >= NTILES) break;
            cur = nxt;
        }
    } else {
        // =================== DP4A PATH (fma pipe) ===================
        // Thread (tr, tc): rows tr*8..tr*8+7, cols {j*16 + tc}.
        // Operands register double-buffered: kw+1's LDS overlap kw's dp4a.
        const int tr = tid >> 4;               // 0..15 -> 8-row group
        const int tc = tid & 15;               // 0..15 -> strided col lane

        while (true) {
            if (tid == 0) sh_next = atomicAdd(&g_next, 1);
            __syncthreads();
            const int t = sh_next;
            __syncthreads();
            if (t >= NTILES) break;

            const int tileM = t >> 4, tileN = t & 15;
            const int rowBase = tileM * BM, colBase = tileN * BN;

            int acc[8][8];
            #pragma unroll
            for (int i = 0; i < 8; i++)
                #pragma unroll
                for (int j = 0; j < 8; j++) acc[i][j] = 0;

            auto load_chunk = [&](int b, int c) {
                #pragma unroll
                for (int u = 0; u < 8; u++) {
                    int idx = u * 256 + tid;
                    int r = (idx & 1023) >> 3, seg = idx & 7;
                    if (idx < 1024) {
                        cp16(smBase + (uint32_t)(b * DBUF + r * XROW + seg * 16),
                             g_xa + (size_t)(rowBase + r) * Kdim + c * 128
                                  + seg * 16);
                    } else {
                        cp16(smBase + (uint32_t)(b * DBUF + WOFF + r * XROW
                                                 + seg * 16),
                             g_wa + (size_t)(colBase + r) * Kdim + c * 128
                                  + seg * 16);
                    }
                }
                asm volatile("cp.async.commit_group;" ::: "memory");
            };

            load_chunk(0, 0);
            for (int c = 0; c < 16; c++) {
                if (c + 1 < 16) {
                    load_chunk((c + 1) & 1, c + 1);
                    asm volatile("cp.async.wait_group 1;" ::: "memory");
                } else {
                    asm volatile("cp.async.wait_group 0;" ::: "memory");
                }
                __syncthreads();

                const char* xb = smraw + (c & 1) * DBUF;
                const char* wb = xb + WOFF;

                int xw[2][8], ww[2][8];
                // prefetch kw = 0 into buffer 0
                #pragma unroll
                for (int i = 0; i < 8; i++)
                    xw[0][i] = *(const int*)(xb + (tr * 8 + i) * XROW);
                #pragma unroll
                for (int j = 0; j < 8; j++)
                    ww[0][j] = *(const int*)(wb + (j * 16 + tc) * XROW);

                #pragma unroll 2
                for (int kw = 0; kw < 32; kw++) {
                    const int cb = kw & 1, nb = cb ^ 1;
                    if (kw < 31) {
                        #pragma unroll
                        for (int i = 0; i < 8; i++)
                            xw[nb][i] = *(const int*)(xb + (tr * 8 + i) * XROW
                                                      + (kw + 1) * 4);
                        #pragma unroll
                        for (int j = 0; j < 8; j++)
                            ww[nb][j] = *(const int*)(wb + (j * 16 + tc) * XROW
                                                      + (kw + 1) * 4);
                    }
                    #pragma unroll
                    for (int i = 0; i < 8; i++)
                        #pragma unroll
                        for (int j = 0; j < 8; j++)
                            acc[i][j] = __dp4a(xw[cb][i], ww[cb][j], acc[i][j]);
                }
                __syncthreads();   // before next load overwrites this buffer
            }

            // ---- epilogue: int16 store + exact int stats via smem ----
            {
                int16_t* grow = g_gemm16
                              + (size_t)(rowBase + tr * 8) * Ndim + colBase;
                #pragma unroll
                for (int i = 0; i < 8; i++) {
                    #pragma unroll
                    for (int j = 0; j < 8; j++)
                        grow[(size_t)i * Ndim + j * 16 + tc] =
                            (int16_t)acc[i][j];
                }

                int* S = reinterpret_cast<int*>(smraw);        // [16][128]
                int* Q = S + 16 * 128;
                #pragma unroll
                for (int j = 0; j < 8; j++) {
                    int s = 0, q = 0;
                    #pragma unroll
                    for (int i = 0; i < 8; i++) {
                        s += acc[i][j];
                        q += acc[i][j] * acc[i][j];
                    }
                    S[tr * 128 + j * 16 + tc] = s;
                    Q[tr * 128 + j * 16 + tc] = q;
                }
                __syncthreads();
                {
                    int h = tid >> 7, cc = tid & 127;
                    int s = 0, q = 0;
                    #pragma unroll
                    for (int k = 0; k < 8; k++) {
                        s += S[(h * 8 + k) * 128 + cc];
                        q += Q[(h * 8 + k) * 128 + cc];
                    }
                    const int chunk = tileM * 2 + h;
                    g_psum_i[(size_t)chunk * Ndim + colBase + cc] = s;
                    g_psq_i [(size_t)chunk * Ndim + colBase + cc] = q;
                }
                __syncthreads();   // protect S/Q region before next tile
            }
        }
    }
}

// ---------------------------------------------------------------------------
// Kernel 5: finalize stats -> per-column scale/shift (exact ints -> double)
// ---------------------------------------------------------------------------
__global__ void finalize_kernel(const float* __restrict__ gamma,
                                const float* __restrict__ beta) {
    int t = threadIdx.x;
    int col = blockIdx.x * 64 + (t >> 2);
    int slice = t & 3;
    int s = 0;
    long long q = 0;
    #pragma unroll 8
    for (int i = slice * 32; i < slice * 32 + 32; i++) {
        s += g_psum_i[(size_t)i * Ndim + col];
        q += (long long)g_psq_i[(size_t)i * Ndim + col];
    }
    s += __shfl_xor_sync(0xffffffffu, s, 1);
    q += __shfl_xor_sync(0xffffffffu, q, 1);
    s += __shfl_xor_sync(0xffffffffu, s, 2);
    q += __shfl_xor_sync(0xffffffffu, q, 2);
    if (slice == 0) {
        double mean = (double)s / (double)Mdim;
        double var  = (double)q / (double)Mdim - mean * mean;
        float inv   = rsqrtf((float)(var + 1e-5));
        float sc    = gamma[col] * inv;
        g_scale[col] = sc;
        g_shift[col] = beta[col] - (float)mean * sc;
    }
}

// ---------------------------------------------------------------------------
// Kernel 6: normalize into d_out (float4 scale/shift loads)
// ---------------------------------------------------------------------------
__global__ void normalize_kernel(float4* __restrict__ out) {
    int i = blockIdx.x * blockDim.x + threadIdx.x;
    int c4 = i & (Ndim / 4 - 1);
    short4 v = reinterpret_cast<const short4*>(g_gemm16)[i];
    float4 sc = reinterpret_cast<const float4*>(g_scale)[c4];
    float4 sh = reinterpret_cast<const float4*>(g_shift)[c4];
    float4 o;
    o.x = (float)v.x * sc.x + sh.x;
    o.y = (float)v.y * sc.y + sh.y;
    o.z = (float)v.z * sc.z + sh.z;
    o.w = (float)v.w * sc.w + sh.w;
    out[i] = o;
}

// ---------------------------------------------------------------------------
// Launch (GEMM at position 4 = ncu's observed capture slot)
// ---------------------------------------------------------------------------
extern "C" void kernel_launch(void* const* d_in, const int* in_sizes, int n_in,
                              void* d_out, int out_size) {
    const float* x     = (const float*)d_in[0];
    const float* w     = (const float*)d_in[1];
    const float* gamma = (const float*)d_in[2];
    const float* beta  = (const float*)d_in[3];
    float* out = (float*)d_out;

    cudaFuncSetAttribute(gemm_kernel,
                         cudaFuncAttributeMaxDynamicSharedMemorySize,
                         GEMM_SMEM);

    binx_kernel<<<(Mdim * Kdim / 4) / 256, 256>>>((const float4*)x);   // 1
    binw_kernel<<<(Ndim * Kdim / 4) / 256, 256>>>((const float4*)w);   // 2
    pad_kernel<<<1, 32>>>();                                           // 3
    gemm_kernel<<<2 * NSM, 256, GEMM_SMEM>>>();                        // 4
    finalize_kernel<<<Ndim / 64, 256>>>(gamma, beta);                  // 5
    normalize_kernel<<<(Mdim * Ndim / 4) / 256, 256>>>((float4*)out);  // 6
}

// round 16
// speedup vs baseline: 1.0100x; 1.0100x over previous
#include <cuda_runtime.h>
#include <cstdint>

// ---------------------------------------------------------------------------
// out = BN( sign(x) @ sign(W)^T ),  x[8192,2048], W[2048,2048] fp32.
// tcgen05 unavailable (harness assembles sm_103). Hybrid two-engine GEMM:
// tensor CTAs (mma.sync, bids 0..147) + dp4a CTAs (fma pipe, bids 148..295)
// from one atomic tile queue. R15 diagnosis: L1tex wavefront pipe is the
// contended resource (66.7%); dp4a scalar LDS generate ~24 wavefronts/kw.
// This round: dp4a uses 128-bit LDS (strided map, no xor) -> ~10 wf/kw.
// Stats exact ints -> bit-identical output under work stealing.
// ---------------------------------------------------------------------------

static constexpr int Mdim = 8192;
static constexpr int Ndim = 2048;
static constexpr int Kdim = 2048;

__device__ int8_t  g_xa[(size_t)Mdim * Kdim];          // 16 MB
__device__ int8_t  g_wa[(size_t)Ndim * Kdim];          //  4 MB
__device__ int16_t g_gemm16[(size_t)Mdim * Ndim];      // 32 MB (|val| <= 2048)
__device__ int     g_psum_i[128 * Ndim];               // per-64-row partials
__device__ int     g_psq_i [128 * Ndim];               // (exact int32)
__device__ float   g_scale[Ndim];
__device__ float   g_shift[Ndim];
__device__ int     g_next;                             // tile work queue

// ---------------------------------------------------------------------------
// Helpers
// ---------------------------------------------------------------------------
__device__ __forceinline__ uint32_t smem_u32(const void* p) {
    uint32_t r;
    asm("{ .reg .u64 t; cvta.to.shared.u64 t, %1; cvt.u32.u64 %0, t; }"
        : "=r"(r) : "l"(p));
    return r;
}

__device__ __forceinline__ void cp16(uint32_t saddr, const void* gaddr) {
    asm volatile("cp.async.cg.shared.global [%0], [%1], 16;"
                 :: "r"(saddr), "l"(gaddr));
}

// SW64 swizzle for 64-byte rows: bits[5:4] ^= bits[8:7]
__device__ __forceinline__ uint32_t swz64(uint32_t off) {
    return off ^ ((off >> 3) & 0x30);
}

#define LDSM_X4(R0, R1, R2, R3, addr)                                        \
    asm volatile("ldmatrix.sync.aligned.m8n8.x4.shared.b16 {%0,%1,%2,%3}, [%4];" \
                 : "=r"(R0), "=r"(R1), "=r"(R2), "=r"(R3) : "r"(addr))

__device__ __forceinline__ void mma_s8(int& c0, int& c1, int& c2, int& c3,
                                       uint32_t a0, uint32_t a1, uint32_t a2,
                                       uint32_t a3, uint32_t b0, uint32_t b1) {
    asm volatile(
        "mma.sync.aligned.m16n8k32.row.col.s32.s8.s8.s32 "
        "{%0,%1,%2,%3}, {%4,%5,%6,%7}, {%8,%9}, {%0,%1,%2,%3};"
        : "+r"(c0), "+r"(c1), "+r"(c2), "+r"(c3)
        : "r"(a0), "r"(a1), "r"(a2), "r"(a3), "r"(b0), "r"(b1));
}

// ---------------------------------------------------------------------------
// Kernels 1/2: binarize fp32 -> int8 {-1, 0, +1}
// ---------------------------------------------------------------------------
__device__ __forceinline__ int8_t sgn8(float a) {
    return (int8_t)((a > 0.0f) ? 1 : ((a < 0.0f) ? -1 : 0));
}

__global__ void binx_kernel(const float4* __restrict__ in) {
    int i = blockIdx.x * blockDim.x + threadIdx.x;
    float4 v = in[i];
    reinterpret_cast<char4*>(g_xa)[i] =
        make_char4(sgn8(v.x), sgn8(v.y), sgn8(v.z), sgn8(v.w));
}

__global__ void binw_kernel(const float4* __restrict__ in) {
    int i = blockIdx.x * blockDim.x + threadIdx.x;
    float4 v = in[i];
    reinterpret_cast<char4*>(g_wa)[i] =
        make_char4(sgn8(v.x), sgn8(v.y), sgn8(v.z), sgn8(v.w));
}

// Resets the work queue each graph replay (also keeps GEMM at ncu slot 4).
__global__ void pad_kernel() {
    if (threadIdx.x == 0) g_next = 0;
}

// ---------------------------------------------------------------------------
// Kernel 4: hybrid persistent GEMM, D = Xa @ Wa^T over 1024 128x128 tiles.
// ---------------------------------------------------------------------------
static constexpr int BM = 128, BN = 128, BK = 64, STAGES = 4;
static constexpr int KT = Kdim / BK;                      // 32 ktiles / tile
static constexpr int NSM = 148;
static constexpr int NTILES = (Mdim / BM) * (Ndim / BN);  // 1024
static constexpr int A_BYTES = BM * BK;                   // 8 KB
static constexpr int B_BYTES = BN * BK;                   // 8 KB
static constexpr int STAGE_BYTES = A_BYTES + B_BYTES;     // 16 KB
// dp4a layout: per buffer, X half 128 rows x 144B (128B data + pad) then W.
static constexpr int XROW  = 144;
static constexpr int WOFF  = 128 * XROW;                  // 18432
static constexpr int DBUF  = 2 * WOFF;                    // 36864 per buffer
static constexpr int GEMM_SMEM = 2 * DBUF;                // 73728 (dyn)

__global__ void __launch_bounds__(256, 2)
gemm_kernel() {
    extern __shared__ __align__(1024) char smraw[];
    __shared__ int sh_next;

    const int tid  = threadIdx.x;
    const int lane = tid & 31;
    const uint32_t smBase = smem_u32(smraw);

    if (blockIdx.x < NSM) {
        // =================== TENSOR PATH ===================
        const int wid  = tid >> 5;
        const int warpM = wid >> 2;            // 0..1 -> 64 rows
        const int warpN = wid & 3;             // 0..3 -> 32 cols

        if (tid == 0) sh_next = atomicAdd(&g_next, 1);
        __syncthreads();
        int cur = sh_next;
        if (cur >= NTILES) return;

        auto load_ts = [&](int s, int t, int kt) {
            const int8_t* gA = g_xa + (size_t)(t >> 4) * BM * Kdim + kt * BK;
            const int8_t* gB = g_wa + (size_t)(t & 15) * BN * Kdim + kt * BK;
            uint32_t aBase = smBase + (uint32_t)s * STAGE_BYTES;
            uint32_t bBase = aBase + A_BYTES;
            #pragma unroll
            for (int i = 0; i < 2; i++) {
                int c = i * 256 + tid;
                int row = c >> 2, seg = c & 3;
                cp16(aBase + swz64((uint32_t)c * 16),
                     gA + (size_t)row * Kdim + seg * 16);
            }
            #pragma unroll
            for (int i = 0; i < 2; i++) {
                int c = i * 256 + tid;
                int row = c >> 2, seg = c & 3;
                cp16(bBase + swz64((uint32_t)c * 16),
                     gB + (size_t)row * Kdim + seg * 16);
            }
            asm volatile("cp.async.commit_group;" ::: "memory");
        };

        const int lrow = (lane & 7) + (((lane >> 3) & 1) << 3);
        const int lkb  = ((lane >> 4) & 1) * 16;
        uint32_t aoff[4], boff[2];
        #pragma unroll
        for (int mi = 0; mi < 4; mi++)
            aoff[mi] = (uint32_t)(warpM * 64 + mi * 16 + lrow) * BK + lkb;
        #pragma unroll
        for (int pb = 0; pb < 2; pb++)
            boff[pb] = (uint32_t)(warpN * 32 + pb * 16 + lrow) * BK + lkb;

        int acc[4][4][4];
        #pragma unroll
        for (int mi = 0; mi < 4; mi++)
            #pragma unroll
            for (int ni = 0; ni < 4; ni++)
                #pragma unroll
                for (int r = 0; r < 4; r++) acc[mi][ni][r] = 0;

        const int erow = lane >> 2;
        const int ecol = (lane & 3) * 2;

        #pragma unroll
        for (int s = 0; s < STAGES - 1; s++) load_ts(s, cur, s);

        int nxt = NTILES;
        while (true) {
            for (int kt = 0; kt < KT; kt++) {
                const int s = kt & (STAGES - 1);
                asm volatile("cp.async.wait_group %0;" :: "n"(STAGES - 2)
                             : "memory");
                __syncthreads();

                const int np = kt + STAGES - 1;
                const int ls = np & (STAGES - 1);
                if (np < KT) {
                    load_ts(ls, cur, np);
                } else {
                    if (np == KT) nxt = sh_next;   // fetched at kt == KT-4
                    if (nxt < NTILES)
                        load_ts(ls, nxt, np - KT);
                    else
                        asm volatile("cp.async.commit_group;" ::: "memory");
                }
                if (kt == KT - 4 && tid == 0)
                    sh_next = atomicAdd(&g_next, 1);

                const uint32_t aBase = smBase + (uint32_t)s * STAGE_BYTES;
                const uint32_t bBase = aBase + A_BYTES;
                #pragma unroll
                for (int k32 = 0; k32 < 2; k32++) {
                    uint32_t a[4][4], b[2][4];
                    #pragma unroll
                    for (int mi = 0; mi < 4; mi++)
                        LDSM_X4(a[mi][0], a[mi][1], a[mi][2], a[mi][3],
                                aBase + swz64(aoff[mi] + k32 * 32));
                    #pragma unroll
                    for (int pb = 0; pb < 2; pb++)
                        LDSM_X4(b[pb][0], b[pb][1], b[pb][2], b[pb][3],
                                bBase + swz64(boff[pb] + k32 * 32));
                    #pragma unroll
                    for (int mi = 0; mi < 4; mi++) {
                        #pragma unroll
                        for (int ni = 0; ni < 4; ni++) {
                            const int pb = ni >> 1, sub = ni & 1;
                            mma_s8(acc[mi][ni][0], acc[mi][ni][1],
                                   acc[mi][ni][2], acc[mi][ni][3],
                                   a[mi][0], a[mi][1], a[mi][2], a[mi][3],
                                   b[pb][sub], b[pb][2 + sub]);
                        }
                    }
                }
            }

            // ---- tile epilogue: int16 store + exact int column stats ----
            {
                const int tileM = cur >> 4, tileN = cur & 15;
                const int rowBase = tileM * BM + warpM * 64;
                const int colBase = tileN * BN + warpN * 32;
                int16_t* gout = g_gemm16 + (size_t)rowBase * Ndim + colBase;
                #pragma unroll
                for (int mi = 0; mi < 4; mi++) {
                    #pragma unroll
                    for (int ni = 0; ni < 4; ni++) {
                        int16_t* p0 = gout + (size_t)(mi * 16 + erow) * Ndim
                                    + ni * 8 + ecol;
                        *reinterpret_cast<short2*>(p0) =
                            make_short2((int16_t)acc[mi][ni][0],
                                        (int16_t)acc[mi][ni][1]);
                        *reinterpret_cast<short2*>(p0 + (size_t)8 * Ndim) =
                            make_short2((int16_t)acc[mi][ni][2],
                                        (int16_t)acc[mi][ni][3]);
                    }
                }
                const int chunk = tileM * 2 + warpM;
                #pragma unroll
                for (int ni = 0; ni < 4; ni++) {
                    int s0 = 0, s1 = 0, q0 = 0, q1 = 0;
                    #pragma unroll
                    for (int mi = 0; mi < 4; mi++) {
                        int a0 = acc[mi][ni][0], a1 = acc[mi][ni][1];
                        int a2 = acc[mi][ni][2], a3 = acc[mi][ni][3];
                        s0 += a0 + a2;  s1 += a1 + a3;
                        q0 += a0 * a0 + a2 * a2;
                        q1 += a1 * a1 + a3 * a3;
                    }
                    #pragma unroll
                    for (int off = 4; off < 32; off <<= 1) {
                        s0 += __shfl_xor_sync(0xffffffffu, s0, off);
                        s1 += __shfl_xor_sync(0xffffffffu, s1, off);
                        q0 += __shfl_xor_sync(0xffffffffu, q0, off);
                        q1 += __shfl_xor_sync(0xffffffffu, q1, off);
                    }
                    if (lane < 4) {
                        int c = colBase + ni * 8 + lane * 2;
                        g_psum_i[(size_t)chunk * Ndim + c]     = s0;
                        g_psum_i[(size_t)chunk * Ndim + c + 1] = s1;
                        g_psq_i [(size_t)chunk * Ndim + c]     = q0;
                        g_psq_i [(size_t)chunk * Ndim + c + 1] = q1;
                    }
                }
                #pragma unroll
                for (int mi = 0; mi < 4; mi++)
                    #pragma unroll
                    for (int ni = 0; ni < 4; ni++)
                        #pragma unroll
                        for (int r = 0; r < 4; r++) acc[mi][ni][r] = 0;
            }

            if (nxt >= NTILES) break;
            cur = nxt;
        }
    } else {
        // =================== DP4A PATH (fma pipe) ===================
        // Thread (tr, tc): rows tr*8..tr*8+7, cols {j*16 + tc}.
        // 128-bit LDS: X v4 broadcast (1 phase), W v4 2-way (4 phases)
        // -> ~10 wavefronts/kw/warp vs 24 scalar.
        const int tr = tid >> 4;               // 0..15 -> 8-row group
        const int tc = tid & 15;               // 0..15 -> strided col lane

        while (true) {
            if (tid == 0) sh_next = atomicAdd(&g_next, 1);
            __syncthreads();
            const int t = sh_next;
            __syncthreads();
            if (t >= NTILES) break;

            const int tileM = t >> 4, tileN = t & 15;
            const int rowBase = tileM * BM, colBase = tileN * BN;

            int acc[8][8];
            #pragma unroll
            for (int i = 0; i < 8; i++)
                #pragma unroll
                for (int j = 0; j < 8; j++) acc[i][j] = 0;

            auto load_chunk = [&](int b, int c) {
                #pragma unroll
                for (int u = 0; u < 8; u++) {
                    int idx = u * 256 + tid;
                    int r = (idx & 1023) >> 3, seg = idx & 7;
                    if (idx < 1024) {
                        cp16(smBase + (uint32_t)(b * DBUF + r * XROW + seg * 16),
                             g_xa + (size_t)(rowBase + r) * Kdim + c * 128
                                  + seg * 16);
                    } else {
                        cp16(smBase + (uint32_t)(b * DBUF + WOFF + r * XROW
                                                 + seg * 16),
                             g_wa + (size_t)(colBase + r) * Kdim + c * 128
                                  + seg * 16);
                    }
                }
                asm volatile("cp.async.commit_group;" ::: "memory");
            };

            load_chunk(0, 0);
            for (int c = 0; c < 16; c++) {
                if (c + 1 < 16) {
                    load_chunk((c + 1) & 1, c + 1);
                    asm volatile("cp.async.wait_group 1;" ::: "memory");
                } else {
                    asm volatile("cp.async.wait_group 0;" ::: "memory");
                }
                __syncthreads();

                const char* xb = smraw + (c & 1) * DBUF;
                const char* wb = xb + WOFF;

                // 8 kw4 groups per 128B chunk; per group: 8 X v4 + 8 W v4
                // + 256 dp4a.
                #pragma unroll 2
                for (int kw4 = 0; kw4 < 8; kw4++) {
                    int4 xv[8];
                    #pragma unroll
                    for (int i = 0; i < 8; i++)
                        xv[i] = *(const int4*)(xb + (tr * 8 + i) * XROW
                                               + kw4 * 16);
                    #pragma unroll
                    for (int j = 0; j < 8; j++) {
                        int4 wv = *(const int4*)(wb + (j * 16 + tc) * XROW
                                                 + kw4 * 16);
                        #pragma unroll
                        for (int i = 0; i < 8; i++) {
                            acc[i][j] = __dp4a(xv[i].x, wv.x, acc[i][j]);
                            acc[i][j] = __dp4a(xv[i].y, wv.y, acc[i][j]);
                            acc[i][j] = __dp4a(xv[i].z, wv.z, acc[i][j]);
                            acc[i][j] = __dp4a(xv[i].w, wv.w, acc[i][j]);
                        }
                    }
                }
                __syncthreads();   // before next load overwrites this buffer
            }

            // ---- epilogue: int16 store + exact int stats via smem ----
            {
                int16_t* grow = g_gemm16
                              + (size_t)(rowBase + tr * 8) * Ndim + colBase;
                #pragma unroll
                for (int i = 0; i < 8; i++) {
                    #pragma unroll
                    for (int j = 0; j < 8; j++)
                        grow[(size_t)i * Ndim + j * 16 + tc] =
                            (int16_t)acc[i][j];
                }

                int* S = reinterpret_cast<int*>(smraw);        // [16][128]
                int* Q = S + 16 * 128;
                #pragma unroll
                for (int j = 0; j < 8; j++) {
                    int s = 0, q = 0;
                    #pragma unroll
                    for (int i = 0; i < 8; i++) {
                        s += acc[i][j];
                        q += acc[i][j] * acc[i][j];
                    }
                    S[tr * 128 + j * 16 + tc] = s;
                    Q[tr * 128 + j * 16 + tc] = q;
                }
                __syncthreads();
                {
                    int h = tid >> 7, cc = tid & 127;
                    int s = 0, q = 0;
                    #pragma unroll
                    for (int k = 0; k < 8; k++) {
                        s += S[(h * 8 + k) * 128 + cc];
                        q += Q[(h * 8 + k) * 128 + cc];
                    }
                    const int chunk = tileM * 2 + h;
                    g_psum_i[(size_t)chunk * Ndim + colBase + cc] = s;
                    g_psq_i [(size_t)chunk * Ndim + colBase + cc] = q;
                }
                __syncthreads();   // protect S/Q region before next tile
            }
        }
    }
}

// ---------------------------------------------------------------------------
// Kernel 5: finalize stats -> per-column scale/shift (exact ints -> double)
// ---------------------------------------------------------------------------
__global__ void finalize_kernel(const float* __restrict__ gamma,
                                const float* __restrict__ beta) {
    int t = threadIdx.x;
    int col = blockIdx.x * 64 + (t >> 2);
    int slice = t & 3;
    int s = 0;
    long long q = 0;
    #pragma unroll 8
    for (int i = slice * 32; i < slice * 32 + 32; i++) {
        s += g_psum_i[(size_t)i * Ndim + col];
        q += (long long)g_psq_i[(size_t)i * Ndim + col];
    }
    s += __shfl_xor_sync(0xffffffffu, s, 1);
    q += __shfl_xor_sync(0xffffffffu, q, 1);
    s += __shfl_xor_sync(0xffffffffu, s, 2);
    q += __shfl_xor_sync(0xffffffffu, q, 2);
    if (slice == 0) {
        double mean = (double)s / (double)Mdim;
        double var  = (double)q / (double)Mdim - mean * mean;
        float inv   = rsqrtf((float)(var + 1e-5));
        float sc    = gamma[col] * inv;
        g_scale[col] = sc;
        g_shift[col] = beta[col] - (float)mean * sc;
    }
}

// ---------------------------------------------------------------------------
// Kernel 6: normalize into d_out (float4 scale/shift loads)
// ---------------------------------------------------------------------------
__global__ void normalize_kernel(float4* __restrict__ out) {
    int i = blockIdx.x * blockDim.x + threadIdx.x;
    int c4 = i & (Ndim / 4 - 1);
    short4 v = reinterpret_cast<const short4*>(g_gemm16)[i];
    float4 sc = reinterpret_cast<const float4*>(g_scale)[c4];
    float4 sh = reinterpret_cast<const float4*>(g_shift)[c4];
    float4 o;
    o.x = (float)v.x * sc.x + sh.x;
    o.y = (float)v.y * sc.y + sh.y;
    o.z = (float)v.z * sc.z + sh.z;
    o.w = (float)v.w * sc.w + sh.w;
    out[i] = o;
}

// ---------------------------------------------------------------------------
// Launch (GEMM at position 4 = ncu's observed capture slot)
// ---------------------------------------------------------------------------
extern "C" void kernel_launch(void* const* d_in, const int* in_sizes, int n_in,
                              void* d_out, int out_size) {
    const float* x     = (const float*)d_in[0];
    const float* w     = (const float*)d_in[1];
    const float* gamma = (const float*)d_in[2];
    const float* beta  = (const float*)d_in[3];
    float* out = (float*)d_out;

    cudaFuncSetAttribute(gemm_kernel,
                         cudaFuncAttributeMaxDynamicSharedMemorySize,
                         GEMM_SMEM);

    binx_kernel<<<(Mdim * Kdim / 4) / 256, 256>>>((const float4*)x);   // 1
    binw_kernel<<<(Ndim * Kdim / 4) / 256, 256>>>((const float4*)w);   // 2
    pad_kernel<<<1, 32>>>();                                           // 3
    gemm_kernel<<<2 * NSM, 256, GEMM_SMEM>>>();                        // 4
    finalize_kernel<<<Ndim / 64, 256>>>(gamma, beta);                  // 5
    normalize_kernel<<<(Mdim * Ndim / 4) / 256, 256>>>((float4*)out);  // 6
}